// round 9
// baseline (speedup 1.0000x reference)
#include <cuda_runtime.h>
#include <cuda_fp16.h>
#include <math.h>

#define B  32
#define S  2048
#define D  64
#define R  4
#define NB 32

// ---------------- scratch (device globals; no allocation) ----------------
__device__ int    g_bucket[B*R*S];            // 1 MB
__device__ int    g_sortidx[B*R*S];           // 1 MB
__device__ float  g_qninv[B*S];               // 256 KB
__device__ __half g_vh[(size_t)B*S*D];        // 8 MB   fp16 copy of value
__device__ __half g_att[(size_t)B*S*R*D];     // 32 MB  [b][t][r][d]
__device__ float  g_lse[B*S*R];               // 1 MB   [b][t][r]

// ---------------- mma / cp.async / ldmatrix helpers ----------------------
__device__ __forceinline__ void mma_tf32(float* c,
                                         unsigned a0, unsigned a1, unsigned a2, unsigned a3,
                                         unsigned b0, unsigned b1)
{
    asm volatile(
        "mma.sync.aligned.m16n8k8.row.col.f32.tf32.tf32.f32 "
        "{%0,%1,%2,%3}, {%4,%5,%6,%7}, {%8,%9}, {%0,%1,%2,%3};"
        : "+f"(c[0]), "+f"(c[1]), "+f"(c[2]), "+f"(c[3])
        : "r"(a0), "r"(a1), "r"(a2), "r"(a3), "r"(b0), "r"(b1));
}

__device__ __forceinline__ void mma_f16(float* c, const unsigned* a,
                                        unsigned b0, unsigned b1)
{
    asm volatile(
        "mma.sync.aligned.m16n8k16.row.col.f32.f16.f16.f32 "
        "{%0,%1,%2,%3}, {%4,%5,%6,%7}, {%8,%9}, {%0,%1,%2,%3};"
        : "+f"(c[0]), "+f"(c[1]), "+f"(c[2]), "+f"(c[3])
        : "r"(a[0]), "r"(a[1]), "r"(a[2]), "r"(a[3]), "r"(b0), "r"(b1));
}

__device__ __forceinline__ void ldsm4(unsigned& r0, unsigned& r1,
                                      unsigned& r2, unsigned& r3, unsigned addr)
{
    asm volatile("ldmatrix.sync.aligned.m8n8.x4.shared.b16 {%0,%1,%2,%3}, [%4];"
                 : "=r"(r0), "=r"(r1), "=r"(r2), "=r"(r3) : "r"(addr));
}

__device__ __forceinline__ void ldsm4t(unsigned& r0, unsigned& r1,
                                       unsigned& r2, unsigned& r3, unsigned addr)
{
    asm volatile("ldmatrix.sync.aligned.m8n8.x4.trans.shared.b16 {%0,%1,%2,%3}, [%4];"
                 : "=r"(r0), "=r"(r1), "=r"(r2), "=r"(r3) : "r"(addr));
}

__device__ __forceinline__ void cpa16(unsigned dst, const void* src) {
    asm volatile("cp.async.cg.shared.global [%0], [%1], 16;" :: "r"(dst), "l"(src));
}
__device__ __forceinline__ void cpa_commit() { asm volatile("cp.async.commit_group;"); }
__device__ __forceinline__ void cpa_wait1()  { asm volatile("cp.async.wait_group 1;"); }
__device__ __forceinline__ void cpa_wait0()  { asm volatile("cp.async.wait_group 0;"); }

__device__ __forceinline__ unsigned h2u(float a, float b) {
    __half2 h = __floats2half2_rn(a, b);
    return *(unsigned*)&h;
}

// ---------------- kernel 0: value -> fp16 --------------------------------
__global__ void __launch_bounds__(256) vconv_kernel(const float* __restrict__ value)
{
    size_t i = ((size_t)blockIdx.x*256 + threadIdx.x)*4;
    float4 v = *(const float4*)&value[i];
    uint2 h;
    h.x = h2u(v.x, v.y);
    h.y = h2u(v.z, v.w);
    *(uint2*)&g_vh[i] = h;
}

// ---------------- kernel 1: hash projection + bucket + key norm ----------
#define SQ_STR 68
#define HASH_SMEM (128*SQ_STR*4 + 64*64*4)   // sQ[128][68] + sR[64][64]

__global__ void __launch_bounds__(128) hash_kernel(const float* __restrict__ query,
                                                   const float* __restrict__ randm)
{
    extern __shared__ float hs[];
    float* sQ = hs;                 // [128][68]
    float* sR = hs + 128*SQ_STR;    // [64][64]  d-major, rk = r*16+k
    const int b   = blockIdx.y;
    const int tid = threadIdx.x;

    for (int i = tid; i < 1024; i += 128)
        *(float4*)&sR[i*4] = *(const float4*)&randm[b*4096 + i*4];
    const size_t qbase = ((size_t)b*S + (size_t)blockIdx.x*128)*D;
    for (int i = tid; i < 2048; i += 128) {           // coalesced float4
        float4 v = *(const float4*)&query[qbase + (size_t)i*4];
        int row = i >> 4, d4 = (i & 15) << 2;
        *(float4*)&sQ[row*SQ_STR + d4] = v;
    }
    __syncthreads();

    const int t = blockIdx.x*128 + tid;
    const float* q = &sQ[tid*SQ_STR];

    float acc[64];
#pragma unroll
    for (int i = 0; i < 64; i++) acc[i] = 0.f;
    float nrm = 0.f;
    for (int d = 0; d < D; d++) {
        float qd = q[d];
        nrm += qd*qd;
        const float4* rr = (const float4*)&sR[d*64];
#pragma unroll
        for (int i4 = 0; i4 < 16; i4++) {
            float4 r4 = rr[i4];
            acc[i4*4+0] += qd * r4.x;
            acc[i4*4+1] += qd * r4.y;
            acc[i4*4+2] += qd * r4.z;
            acc[i4*4+3] += qd * r4.w;
        }
    }
    g_qninv[b*S + t] = rsqrtf(fmaxf(nrm, 1e-12f));

#pragma unroll
    for (int r = 0; r < R; r++) {
        float bv = acc[r*16];
        int   bi = 0;
#pragma unroll
        for (int k = 1; k < 16; k++) {
            float v = acc[r*16 + k];
            if (v > bv) { bv = v; bi = k; }
        }
#pragma unroll
        for (int k = 0; k < 16; k++) {
            float v = -acc[r*16 + k];
            if (v > bv) { bv = v; bi = 16 + k; }
        }
        g_bucket[(b*R + r)*S + t] = bi;
    }
}

// ---------------- kernel 2: stable counting sort per (b, r) --------------
__global__ void sort_kernel()
{
    __shared__ int hist[NB*256];   // bucket-major, thread-minor
    __shared__ int wtot[8];
    const int br  = blockIdx.x;
    const int tid = threadIdx.x;
    const int* bk = g_bucket  + br*S;
    int*     sidx = g_sortidx + br*S;

    for (int i = tid; i < NB*256; i += 256) hist[i] = 0;
    __syncthreads();

    const int base = tid*8;
    int myb[8];
#pragma unroll
    for (int k = 0; k < 8; k++) { myb[k] = bk[base + k]; hist[myb[k]*256 + tid]++; }
    __syncthreads();

    // exclusive scan over 8192 entries in index order (stable)
    int run = 0;
    for (int i = tid*32; i < tid*32 + 32; i++) { int v = hist[i]; hist[i] = run; run += v; }
    const int lane = tid & 31, wid = tid >> 5;
    int x = run;
#pragma unroll
    for (int off = 1; off < 32; off <<= 1) {
        int nv = __shfl_up_sync(0xffffffffu, x, off);
        if (lane >= off) x += nv;
    }
    if (lane == 31) wtot[wid] = x;
    __syncthreads();
    if (tid < 8) {
        int y = wtot[tid], z = y;
#pragma unroll
        for (int off = 1; off < 8; off <<= 1) {
            int nv = __shfl_up_sync(0x000000ffu, z, off);
            if (tid >= off) z += nv;
        }
        wtot[tid] = z - y;    // exclusive warp offsets
    }
    __syncthreads();
    const int add = (x - run) + wtot[wid];
    for (int i = tid*32; i < tid*32 + 32; i++) hist[i] += add;
    __syncthreads();

#pragma unroll
    for (int k = 0; k < 8; k++) {
        int bb  = myb[k];
        int rnk = hist[bb*256 + tid]++;
        sidx[rnk] = base + k;
    }
}

// ---------------- kernel 3: bucketed attention ---------------------------
// GEMM1 tf32 (K/Q tile fp32), GEMM2 fp16 (P in registers, V fp16 tile).
// smem layout (bytes):
//   [0,2048)        kiS   : int[512]          window key positions, per round
//   [2048,4096)     cinvS : float[512]        1/duplicate-count
//   [4096,6144)     scS   : float[512]        per-key qn*0.125 scale
//   [6144,7168)     statS : float2[64][2]     per-row (m,s) per warp-half
//   [7168,41984)    ksA   : float[128][68]    K window tile (rows 64.. = Q)
//   [41984,64512)   vsh   : half[128][88]     V tile fp16 (176B rows)
//   [64512,81408)   sred  : float[64][66]     GEMM2 partial-sum exchange
//                   (cnt int[2048] aliases sred, phase 0 only)
#define KS_STR  68
#define VSH_STR 88
#define SR_STR  66
#define OFF_KI    0
#define OFF_CINV  2048
#define OFF_SC    4096
#define OFF_STATS 6144
#define OFF_KS    7168
#define OFF_VS    41984
#define OFF_SRED  64512
#define ATTN_SMEM 81408

__global__ void __launch_bounds__(256, 2) attn_kernel(const float* __restrict__ query)
{
    extern __shared__ char smem[];
    int*    kiS   = (int*)   (smem + OFF_KI);
    float*  cinvS = (float*) (smem + OFF_CINV);
    float*  scS   = (float*) (smem + OFF_SC);
    float2* statS = (float2*)(smem + OFF_STATS);
    float*  ksA   = (float*) (smem + OFF_KS);
    float*  sred  = (float*) (smem + OFF_SRED);
    int*    cnt   = (int*)   (smem + OFF_SRED);   // alias (phase 0 only)

    const int blk = blockIdx.x;
    const int b   = blk >> 5;
    const int n   = blk & 31;
    const int tid = threadIdx.x;
    const int l   = tid & 31;
    const int w   = tid >> 5;
    const int mi  = w & 3;     // m-tile (16 rows)
    const int nh  = w >> 2;    // k-half for GEMM2 / n-half for GEMM1

    const int* sidx_b = g_sortidx + b*R*S;
    const int  prev   = (n + 31) & 31;
    const float* qn   = g_qninv + b*S;
    const float* Q    = query + (size_t)b*S*D;
    const __half* Vh  = g_vh  + (size_t)b*S*D;

    const unsigned ks_s = (unsigned)__cvta_generic_to_shared(ksA);
    const unsigned vs_s = (unsigned)__cvta_generic_to_shared(smem + OFF_VS);
    const int i0 = mi*16 + (l>>2);

    // per-lane ldmatrix base addresses (bytes)
    const int lrow = l & 15;
    const int lcol = (l & 16) ? 4 : 0;
    const unsigned aG1 = ks_s + (unsigned)((64 + mi*16 + lrow)*KS_STR + lcol)*4;
    const unsigned bG1 = ks_s + (unsigned)((nh*64 + (l & 7))*KS_STR + ((l >> 3) & 3)*4)*4;
    // V b-frags: matrices {k0..7,n0..7},{k8..15,n0..7},{k0..7,n8..15},{k8..15,n8..15}
    const unsigned bG2 = vs_s + (unsigned)((nh*64 + (l & 15))*VSH_STR)*2 + ((l >> 4) << 4);

    // ---- phase 0a: window key positions ----
    for (int idx = tid; idx < 512; idx += 256) {
        int r = idx >> 7, j = idx & 127;
        int slot = (j < 64) ? (prev*64 + j) : (n*64 + j - 64);
        kiS[idx] = sidx_b[r*S + slot];
    }
    __syncthreads();

    // ---- prologue: start round-0 loads (overlap with counting) ----
    {
        const int* ki = kiS;   // r = 0
#pragma unroll
        for (int it = 0; it < 8; it++) {
            int idx = it*256 + tid, row = idx >> 4, c4 = (idx & 15) << 2;
            cpa16(ks_s + (unsigned)(row*KS_STR + c4)*4, &Q[(size_t)ki[row]*D + c4]);
        }
        cpa_commit();
#pragma unroll
        for (int it = 0; it < 4; it++) {         // 1024 x 16B (fp16 tile)
            int idx = it*256 + tid, row = idx >> 3, c8 = (idx & 7) << 3;
            cpa16(vs_s + (unsigned)row*(VSH_STR*2) + c8*2, &Vh[(size_t)ki[row]*D + c8]);
        }
        cpa_commit();
    }

    // ---- phase 0b: multiplicity counts + scales (cnt lives in sred) ----
    for (int idx = tid; idx < 2048; idx += 256) cnt[idx] = 0;
    __syncthreads();
    for (int idx = tid; idx < 512; idx += 256) atomicAdd(&cnt[kiS[idx]], 1);
    __syncthreads();
    for (int idx = tid; idx < 512; idx += 256) {
        int kp = kiS[idx];
        cinvS[idx] = 1.f / (float)cnt[kp];
        scS[idx]   = qn[kp] * 0.125f;
    }

    for (int r = 0; r < R; r++) {
        const int* ki = kiS + r*128;

        // ---- K(r) ready (oldest outstanding group) ----
        cpa_wait1();
        __syncthreads();

        // ---- GEMM1: S[64x128] = Q(rows 64..127 of ksA) . K^T (tf32) ----
        float acc[8][4];
#pragma unroll
        for (int t2 = 0; t2 < 8; t2++)
#pragma unroll
            for (int c = 0; c < 4; c++) acc[t2][c] = 0.f;

#pragma unroll
        for (int kp = 0; kp < 4; kp++) {            // kk = 2kp, 2kp+1
            unsigned a0,a1,a2,a3, a4,a5,a6,a7;
            ldsm4(a0,a1,a2,a3, aG1 + kp*64);
            ldsm4(a4,a5,a6,a7, aG1 + kp*64 + 32);
#pragma unroll
            for (int nt = 0; nt < 8; nt++) {
                unsigned b0,b1,b2,b3;
                ldsm4(b0,b1,b2,b3, bG1 + (unsigned)(nt*8*KS_STR)*4 + kp*64);
                mma_tf32(acc[nt], a0,a1,a2,a3, b0,b1);
                mma_tf32(acc[nt], a4,a5,a6,a7, b2,b3);
            }
        }

        // ---- in-register scale + masks + local softmax stats ----
        const int qpos0 = ki[64 + i0];
        const int qpos1 = ki[64 + i0 + 8];
        float m0 = -3.4e38f, m1 = -3.4e38f;
#pragma unroll
        for (int nt = 0; nt < 8; nt++) {
#pragma unroll
            for (int e = 0; e < 2; e++) {
                int col = nh*64 + nt*8 + 2*(l&3) + e;
                int kp  = ki[col];
                float sc = scS[r*128 + col];
                float x = acc[nt][e] * sc;
                if      (qpos0 <  kp) x = -1.0e9f;
                else if (qpos0 == kp) x = -1.0e5f;
                acc[nt][e] = x; m0 = fmaxf(m0, x);
                float y = acc[nt][2+e] * sc;
                if      (qpos1 <  kp) y = -1.0e9f;
                else if (qpos1 == kp) y = -1.0e5f;
                acc[nt][2+e] = y; m1 = fmaxf(m1, y);
            }
        }
        m0 = fmaxf(m0, __shfl_xor_sync(0xffffffffu, m0, 1));
        m0 = fmaxf(m0, __shfl_xor_sync(0xffffffffu, m0, 2));
        m1 = fmaxf(m1, __shfl_xor_sync(0xffffffffu, m1, 1));
        m1 = fmaxf(m1, __shfl_xor_sync(0xffffffffu, m1, 2));
        float s0 = 0.f, s1 = 0.f;
#pragma unroll
        for (int nt = 0; nt < 8; nt++)
#pragma unroll
            for (int e = 0; e < 2; e++) {
                float ex = __expf(acc[nt][e]   - m0); acc[nt][e]   = ex; s0 += ex;
                float ey = __expf(acc[nt][2+e] - m1); acc[nt][2+e] = ey; s1 += ey;
            }
        s0 += __shfl_xor_sync(0xffffffffu, s0, 1);
        s0 += __shfl_xor_sync(0xffffffffu, s0, 2);
        s1 += __shfl_xor_sync(0xffffffffu, s1, 1);
        s1 += __shfl_xor_sync(0xffffffffu, s1, 2);
        if ((l & 3) == 0) {
            statS[i0*2 + nh]       = make_float2(m0, s0);
            statS[(i0 + 8)*2 + nh] = make_float2(m1, s1);
        }
        __syncthreads();   // stats visible; all GEMM1 ksA reads done

        // ---- prefetch K(r+1) into ksA (overlaps softmax tail + GEMM2) ----
        if (r < R-1) {
            const int* kin = kiS + (r+1)*128;
#pragma unroll
            for (int it = 0; it < 8; it++) {
                int idx = it*256 + tid, row = idx >> 4, c4 = (idx & 15) << 2;
                cpa16(ks_s + (unsigned)(row*KS_STR + c4)*4, &Q[(size_t)kin[row]*D + c4]);
            }
            cpa_commit();
        }

        float2 ha = statS[i0*2],       hb = statS[i0*2 + 1];
        float M0 = fmaxf(ha.x, hb.x);
        float S0 = ha.y*__expf(ha.x - M0) + hb.y*__expf(hb.x - M0);
        float2 hc = statS[(i0+8)*2],   hd = statS[(i0+8)*2 + 1];
        float M1 = fmaxf(hc.x, hd.x);
        float S1 = hc.y*__expf(hc.x - M1) + hd.y*__expf(hd.x - M1);
        const float f0 = __expf(m0 - M0) / S0;
        const float f1 = __expf(m1 - M1) / S1;

        // ---- pack P into fp16 A-fragments (k16 chunks; no smem!) ----
        // chunk t covers window cols nh*64 + 16t .. +15 (tiles 2t, 2t+1)
        unsigned ra[4][4];
#pragma unroll
        for (int t = 0; t < 4; t++) {
            int col0 = nh*64 + 16*t + 2*(l&3);
            float2 ci = *(float2*)&cinvS[r*128 + col0];
            float2 cj = *(float2*)&cinvS[r*128 + col0 + 8];
            ra[t][0] = h2u(acc[2*t][0]*f0*ci.x,   acc[2*t][1]*f0*ci.y);
            ra[t][1] = h2u(acc[2*t][2]*f1*ci.x,   acc[2*t][3]*f1*ci.y);
            ra[t][2] = h2u(acc[2*t+1][0]*f0*cj.x, acc[2*t+1][1]*f0*cj.y);
            ra[t][3] = h2u(acc[2*t+1][2]*f1*cj.x, acc[2*t+1][3]*f1*cj.y);
        }
        if (((l & 3) == 0) && nh == 0) {
            g_lse[((size_t)b*S + qpos0)*R + r] = M0 + __logf(S0);
            g_lse[((size_t)b*S + qpos1)*R + r] = M1 + __logf(S1);
        }

        // ---- V(r) ready ----
        if (r < R-1) cpa_wait1(); else cpa_wait0();
        __syncthreads();   // vsh visible; sred free (prev round's reads done)

        // ---- GEMM2 (fp16): warp computes all 64 dims over its 64-key half
        float acc2[8][4];
#pragma unroll
        for (int t2 = 0; t2 < 8; t2++)
#pragma unroll
            for (int c = 0; c < 4; c++) acc2[t2][c] = 0.f;

#pragma unroll
        for (int t = 0; t < 4; t++) {
#pragma unroll
            for (int p = 0; p < 4; p++) {          // dim tiles 2p, 2p+1
                unsigned b0,b1,b2,b3;
                ldsm4t(b0,b1,b2,b3, bG2 + (unsigned)(t*16*VSH_STR)*2 + p*32);
                mma_f16(acc2[2*p],   ra[t], b0, b1);
                mma_f16(acc2[2*p+1], ra[t], b2, b3);
            }
        }

        // ---- cross-warp k-half reduction via sred ----
        if (nh == 0) {
#pragma unroll
            for (int j = 0; j < 8; j++) {
                int c0 = j*8 + 2*(l&3);
                *(float2*)&sred[i0*SR_STR + c0]     = make_float2(acc2[j][0], acc2[j][1]);
                *(float2*)&sred[(i0+8)*SR_STR + c0] = make_float2(acc2[j][2], acc2[j][3]);
            }
        }
        __syncthreads();
        if (nh == 1) {
            __half* o0 = g_att + (((size_t)b*S + qpos0)*R + r)*D;
            __half* o1 = g_att + (((size_t)b*S + qpos1)*R + r)*D;
#pragma unroll
            for (int j = 0; j < 8; j++) {
                int c0 = j*8 + 2*(l&3);
                float2 p0 = *(float2*)&sred[i0*SR_STR + c0];
                float2 p1 = *(float2*)&sred[(i0+8)*SR_STR + c0];
                *(__half2*)&o0[c0] = __floats2half2_rn(acc2[j][0]+p0.x, acc2[j][1]+p0.y);
                *(__half2*)&o1[c0] = __floats2half2_rn(acc2[j][2]+p1.x, acc2[j][3]+p1.y);
            }
        }
        __syncthreads();   // all vsh reads + sred reads done

        // ---- prefetch V(r+1) into vsh (overlaps next round's GEMM1) ----
        if (r < R-1) {
            const int* kin = kiS + (r+1)*128;
#pragma unroll
            for (int it = 0; it < 4; it++) {
                int idx = it*256 + tid, row = idx >> 3, c8 = (idx & 7) << 3;
                cpa16(vs_s + (unsigned)row*(VSH_STR*2) + c8*2, &Vh[(size_t)kin[row]*D + c8]);
            }
            cpa_commit();
        }
    }
}

// ---------------- kernel 4: per-position round combine (fp16 att) --------
__global__ void __launch_bounds__(256) combine_kernel(float* __restrict__ out)
{
    const int tid = threadIdx.x;
    const int d2  = tid & 31;                       // half2 index (2 dims)
    const int row = blockIdx.x*8 + (tid >> 5);      // b*S + t
    float4 lv = *(const float4*)(g_lse + (size_t)row*R);
    float m  = fmaxf(fmaxf(lv.x, lv.y), fmaxf(lv.z, lv.w));
    float w0 = __expf(lv.x - m), w1 = __expf(lv.y - m);
    float w2 = __expf(lv.z - m), w3 = __expf(lv.w - m);
    float inv = 1.f / (w0 + w1 + w2 + w3);
    const __half2* a = (const __half2*)g_att + (size_t)row*R*(D/2);
    float2 a0 = __half22float2(a[0*(D/2) + d2]);
    float2 a1 = __half22float2(a[1*(D/2) + d2]);
    float2 a2 = __half22float2(a[2*(D/2) + d2]);
    float2 a3 = __half22float2(a[3*(D/2) + d2]);
    float2 res;
    res.x = (a0.x*w0 + a1.x*w1 + a2.x*w2 + a3.x*w3) * inv;
    res.y = (a0.y*w0 + a1.y*w1 + a2.y*w2 + a3.y*w3) * inv;
    *(float2*)&out[(size_t)row*D + d2*2] = res;
}

// ---------------- launch --------------------------------------------------
extern "C" void kernel_launch(void* const* d_in, const int* in_sizes, int n_in,
                              void* d_out, int out_size)
{
    const float* query = (const float*)d_in[0];
    const float* value = (const float*)d_in[1];
    const float* randm = (const float*)d_in[2];
    float* out = (float*)d_out;

    cudaFuncSetAttribute(hash_kernel,
                         cudaFuncAttributeMaxDynamicSharedMemorySize, HASH_SMEM);
    cudaFuncSetAttribute(attn_kernel,
                         cudaFuncAttributeMaxDynamicSharedMemorySize, ATTN_SMEM);

    vconv_kernel<<<(B*S*D)/(256*4), 256>>>(value);
    hash_kernel<<<dim3(S/128, B), 128, HASH_SMEM>>>(query, randm);
    sort_kernel<<<B*R, 256>>>();
    attn_kernel<<<B*NB, 256, ATTN_SMEM>>>(query);
    combine_kernel<<<(B*S)/8, 256>>>(out);
}

// round 10
// speedup vs baseline: 1.0588x; 1.0588x over previous
#include <cuda_runtime.h>
#include <cuda_fp16.h>
#include <math.h>

#define B  32
#define S  2048
#define D  64
#define R  4
#define NB 32

// ---------------- scratch (device globals; no allocation) ----------------
__device__ int    g_bucket[B*R*S];            // 1 MB
__device__ int    g_sortidx[B*R*S];           // 1 MB
__device__ float  g_qninv[B*S];               // 256 KB
__device__ __half g_qh[(size_t)B*S*D];        // 8 MB   fp16 copy of query
__device__ __half g_vh[(size_t)B*S*D];        // 8 MB   fp16 copy of value
__device__ __half g_att[(size_t)B*S*R*D];     // 32 MB  [b][t][r][d]
__device__ float  g_lse[B*S*R];               // 1 MB   [b][t][r]

// ---------------- mma / cp.async / ldmatrix helpers ----------------------
__device__ __forceinline__ void mma_f16(float* c, const unsigned* a,
                                        unsigned b0, unsigned b1)
{
    asm volatile(
        "mma.sync.aligned.m16n8k16.row.col.f32.f16.f16.f32 "
        "{%0,%1,%2,%3}, {%4,%5,%6,%7}, {%8,%9}, {%0,%1,%2,%3};"
        : "+f"(c[0]), "+f"(c[1]), "+f"(c[2]), "+f"(c[3])
        : "r"(a[0]), "r"(a[1]), "r"(a[2]), "r"(a[3]), "r"(b0), "r"(b1));
}

__device__ __forceinline__ void ldsm4(unsigned& r0, unsigned& r1,
                                      unsigned& r2, unsigned& r3, unsigned addr)
{
    asm volatile("ldmatrix.sync.aligned.m8n8.x4.shared.b16 {%0,%1,%2,%3}, [%4];"
                 : "=r"(r0), "=r"(r1), "=r"(r2), "=r"(r3) : "r"(addr));
}

__device__ __forceinline__ void ldsm4t(unsigned& r0, unsigned& r1,
                                       unsigned& r2, unsigned& r3, unsigned addr)
{
    asm volatile("ldmatrix.sync.aligned.m8n8.x4.trans.shared.b16 {%0,%1,%2,%3}, [%4];"
                 : "=r"(r0), "=r"(r1), "=r"(r2), "=r"(r3) : "r"(addr));
}

__device__ __forceinline__ void cpa16(unsigned dst, const void* src) {
    asm volatile("cp.async.cg.shared.global [%0], [%1], 16;" :: "r"(dst), "l"(src));
}
__device__ __forceinline__ void cpa_commit() { asm volatile("cp.async.commit_group;"); }
__device__ __forceinline__ void cpa_wait1()  { asm volatile("cp.async.wait_group 1;"); }
__device__ __forceinline__ void cpa_wait0()  { asm volatile("cp.async.wait_group 0;"); }

__device__ __forceinline__ unsigned h2u(float a, float b) {
    __half2 h = __floats2half2_rn(a, b);
    return *(unsigned*)&h;
}

// ---------------- kernel 0: value -> fp16 --------------------------------
__global__ void __launch_bounds__(256) vconv_kernel(const float* __restrict__ value)
{
    size_t i = ((size_t)blockIdx.x*256 + threadIdx.x)*4;
    float4 v = *(const float4*)&value[i];
    uint2 h;
    h.x = h2u(v.x, v.y);
    h.y = h2u(v.z, v.w);
    *(uint2*)&g_vh[i] = h;
}

// ---------------- kernel 1: hash + bucket + key norm + Q->fp16 -----------
#define SQ_STR 68
#define HASH_SMEM (128*SQ_STR*4 + 64*64*4)   // sQ[128][68] + sR[64][64]

__global__ void __launch_bounds__(128) hash_kernel(const float* __restrict__ query,
                                                   const float* __restrict__ randm)
{
    extern __shared__ float hs[];
    float* sQ = hs;                 // [128][68]
    float* sR = hs + 128*SQ_STR;    // [64][64]  d-major, rk = r*16+k
    const int b   = blockIdx.y;
    const int tid = threadIdx.x;

    for (int i = tid; i < 1024; i += 128)
        *(float4*)&sR[i*4] = *(const float4*)&randm[b*4096 + i*4];
    const size_t qbase = ((size_t)b*S + (size_t)blockIdx.x*128)*D;
    for (int i = tid; i < 2048; i += 128) {           // coalesced float4
        float4 v = *(const float4*)&query[qbase + (size_t)i*4];
        int row = i >> 4, d4 = (i & 15) << 2;
        *(float4*)&sQ[row*SQ_STR + d4] = v;
        uint2 h;                                      // emit fp16 copy
        h.x = h2u(v.x, v.y);
        h.y = h2u(v.z, v.w);
        *(uint2*)&g_qh[qbase + (size_t)i*4] = h;
    }
    __syncthreads();

    const int t = blockIdx.x*128 + tid;
    const float* q = &sQ[tid*SQ_STR];

    float acc[64];
#pragma unroll
    for (int i = 0; i < 64; i++) acc[i] = 0.f;
    float nrm = 0.f;
    for (int d = 0; d < D; d++) {
        float qd = q[d];
        nrm += qd*qd;
        const float4* rr = (const float4*)&sR[d*64];
#pragma unroll
        for (int i4 = 0; i4 < 16; i4++) {
            float4 r4 = rr[i4];
            acc[i4*4+0] += qd * r4.x;
            acc[i4*4+1] += qd * r4.y;
            acc[i4*4+2] += qd * r4.z;
            acc[i4*4+3] += qd * r4.w;
        }
    }
    g_qninv[b*S + t] = rsqrtf(fmaxf(nrm, 1e-12f));

#pragma unroll
    for (int r = 0; r < R; r++) {
        float bv = acc[r*16];
        int   bi = 0;
#pragma unroll
        for (int k = 1; k < 16; k++) {
            float v = acc[r*16 + k];
            if (v > bv) { bv = v; bi = k; }
        }
#pragma unroll
        for (int k = 0; k < 16; k++) {
            float v = -acc[r*16 + k];
            if (v > bv) { bv = v; bi = 16 + k; }
        }
        g_bucket[(b*R + r)*S + t] = bi;
    }
}

// ---------------- kernel 2: stable counting sort per (b, r) --------------
__global__ void sort_kernel()
{
    __shared__ int hist[NB*256];   // bucket-major, thread-minor
    __shared__ int wtot[8];
    const int br  = blockIdx.x;
    const int tid = threadIdx.x;
    const int* bk = g_bucket  + br*S;
    int*     sidx = g_sortidx + br*S;

    for (int i = tid; i < NB*256; i += 256) hist[i] = 0;
    __syncthreads();

    const int base = tid*8;
    int myb[8];
#pragma unroll
    for (int k = 0; k < 8; k++) { myb[k] = bk[base + k]; hist[myb[k]*256 + tid]++; }
    __syncthreads();

    // exclusive scan over 8192 entries in index order (stable)
    int run = 0;
    for (int i = tid*32; i < tid*32 + 32; i++) { int v = hist[i]; hist[i] = run; run += v; }
    const int lane = tid & 31, wid = tid >> 5;
    int x = run;
#pragma unroll
    for (int off = 1; off < 32; off <<= 1) {
        int nv = __shfl_up_sync(0xffffffffu, x, off);
        if (lane >= off) x += nv;
    }
    if (lane == 31) wtot[wid] = x;
    __syncthreads();
    if (tid < 8) {
        int y = wtot[tid], z = y;
#pragma unroll
        for (int off = 1; off < 8; off <<= 1) {
            int nv = __shfl_up_sync(0x000000ffu, z, off);
            if (tid >= off) z += nv;
        }
        wtot[tid] = z - y;    // exclusive warp offsets
    }
    __syncthreads();
    const int add = (x - run) + wtot[wid];
    for (int i = tid*32; i < tid*32 + 32; i++) hist[i] += add;
    __syncthreads();

#pragma unroll
    for (int k = 0; k < 8; k++) {
        int bb  = myb[k];
        int rnk = hist[bb*256 + tid]++;
        sidx[rnk] = base + k;
    }
}

// ---------------- kernel 3: bucketed attention, all-fp16 MMA -------------
// GEMM1 fp16 (Q/K tile fp16, scale applied post-mma), GEMM2 fp16
// (P in registers, V fp16 tile). smem layout (bytes):
//   [0,2048)        kiS   : int[512]          window key positions, per round
//   [2048,4096)     cinvS : float[512]        1/duplicate-count
//   [4096,6144)     scS   : float[512]        per-key qn*0.125 scale
//   [6144,7168)     statS : float2[64][2]     per-row (m,s) per warp-half
//   [7168,29696)    ksh   : half[128][88]     Q/K window tile (rows 64.. = Q)
//   [29696,52224)   vsh   : half[128][88]     V tile
//   [52224,69120)   sred  : float[64][66]     GEMM2 partial-sum exchange
//                   (cnt int[2048] aliases sred, phase 0 only)
#define KSH_STR 88
#define VSH_STR 88
#define SR_STR  66
#define OFF_KI    0
#define OFF_CINV  2048
#define OFF_SC    4096
#define OFF_STATS 6144
#define OFF_KS    7168
#define OFF_VS    29696
#define OFF_SRED  52224
#define ATTN_SMEM 69120

__global__ void __launch_bounds__(256, 2) attn_kernel()
{
    extern __shared__ char smem[];
    int*    kiS   = (int*)   (smem + OFF_KI);
    float*  cinvS = (float*) (smem + OFF_CINV);
    float*  scS   = (float*) (smem + OFF_SC);
    float2* statS = (float2*)(smem + OFF_STATS);
    float*  sred  = (float*) (smem + OFF_SRED);
    int*    cnt   = (int*)   (smem + OFF_SRED);   // alias (phase 0 only)

    const int blk = blockIdx.x;
    const int b   = blk >> 5;
    const int n   = blk & 31;
    const int tid = threadIdx.x;
    const int l   = tid & 31;
    const int w   = tid >> 5;
    const int mi  = w & 3;     // m-tile (16 rows)
    const int nh  = w >> 2;    // k-half for GEMM2 / n-half for GEMM1

    const int* sidx_b = g_sortidx + b*R*S;
    const int  prev   = (n + 31) & 31;
    const float* qn   = g_qninv + b*S;
    const __half* Qh  = g_qh + (size_t)b*S*D;
    const __half* Vh  = g_vh + (size_t)b*S*D;

    const unsigned ks_s = (unsigned)__cvta_generic_to_shared(smem + OFF_KS);
    const unsigned vs_s = (unsigned)__cvta_generic_to_shared(smem + OFF_VS);
    const int i0 = mi*16 + (l>>2);

    // per-lane ldmatrix base addresses (bytes)
    // A (Q rows 64+): matrices (m0-7,k0-7),(m8-15,k0-7),(m0-7,k8-15),(m8-15,k8-15)
    const unsigned aG1 = ks_s + (unsigned)((64 + mi*16 + (l & 15))*KSH_STR)*2
                              + ((l >> 4) << 4);
    // B (K rows): matrices (nA,k0-7),(nA,k8-15),(nB,k0-7),(nB,k8-15)
    const unsigned bG1 = ks_s + (unsigned)((nh*64 + (l & 7) + ((l & 16) >> 1))*KSH_STR)*2
                              + (((l >> 3) & 1) << 4);
    // V b-frags (trans): matrices {k0-7,n0-7},{k8-15,n0-7},{k0-7,n8-15},{k8-15,n8-15}
    const unsigned bG2 = vs_s + (unsigned)((nh*64 + (l & 15))*VSH_STR)*2 + ((l >> 4) << 4);

    // ---- phase 0a: window key positions ----
    for (int idx = tid; idx < 512; idx += 256) {
        int r = idx >> 7, j = idx & 127;
        int slot = (j < 64) ? (prev*64 + j) : (n*64 + j - 64);
        kiS[idx] = sidx_b[r*S + slot];
    }
    __syncthreads();

    // ---- prologue: start round-0 loads (overlap with counting) ----
    {
        const int* ki = kiS;   // r = 0
#pragma unroll
        for (int it = 0; it < 4; it++) {         // 1024 x 16B
            int idx = it*256 + tid, row = idx >> 3, c8 = (idx & 7) << 3;
            cpa16(ks_s + (unsigned)row*(KSH_STR*2) + c8*2, &Qh[(size_t)ki[row]*D + c8]);
        }
        cpa_commit();
#pragma unroll
        for (int it = 0; it < 4; it++) {
            int idx = it*256 + tid, row = idx >> 3, c8 = (idx & 7) << 3;
            cpa16(vs_s + (unsigned)row*(VSH_STR*2) + c8*2, &Vh[(size_t)ki[row]*D + c8]);
        }
        cpa_commit();
    }

    // ---- phase 0b: multiplicity counts + scales (cnt lives in sred) ----
    for (int idx = tid; idx < 2048; idx += 256) cnt[idx] = 0;
    __syncthreads();
    for (int idx = tid; idx < 512; idx += 256) atomicAdd(&cnt[kiS[idx]], 1);
    __syncthreads();
    for (int idx = tid; idx < 512; idx += 256) {
        int kp = kiS[idx];
        cinvS[idx] = 1.f / (float)cnt[kp];
        scS[idx]   = qn[kp] * 0.125f;
    }

    for (int r = 0; r < R; r++) {
        const int* ki = kiS + r*128;

        // ---- K(r) ready (oldest outstanding group) ----
        cpa_wait1();
        __syncthreads();

        // ---- GEMM1 (fp16): S[64x128] = Q(rows 64..127) . K^T ----
        float acc[8][4];
#pragma unroll
        for (int t2 = 0; t2 < 8; t2++)
#pragma unroll
            for (int c = 0; c < 4; c++) acc[t2][c] = 0.f;

        unsigned af[4][4];                           // A frags, 4 k16 chunks
#pragma unroll
        for (int c = 0; c < 4; c++)
            ldsm4(af[c][0], af[c][1], af[c][2], af[c][3], aG1 + c*32);

#pragma unroll
        for (int p = 0; p < 4; p++) {                // n-tile pairs 2p, 2p+1
#pragma unroll
            for (int c = 0; c < 4; c++) {            // k16 chunks
                unsigned b0,b1,b2,b3;
                ldsm4(b0,b1,b2,b3, bG1 + (unsigned)(p*16*KSH_STR)*2 + c*32);
                mma_f16(acc[2*p],   af[c], b0, b1);
                mma_f16(acc[2*p+1], af[c], b2, b3);
            }
        }

        // ---- in-register scale + masks + local softmax stats ----
        const int qpos0 = ki[64 + i0];
        const int qpos1 = ki[64 + i0 + 8];
        float m0 = -3.4e38f, m1 = -3.4e38f;
#pragma unroll
        for (int nt = 0; nt < 8; nt++) {
#pragma unroll
            for (int e = 0; e < 2; e++) {
                int col = nh*64 + nt*8 + 2*(l&3) + e;
                int kp  = ki[col];
                float sc = scS[r*128 + col];
                float x = acc[nt][e] * sc;
                if      (qpos0 <  kp) x = -1.0e9f;
                else if (qpos0 == kp) x = -1.0e5f;
                acc[nt][e] = x; m0 = fmaxf(m0, x);
                float y = acc[nt][2+e] * sc;
                if      (qpos1 <  kp) y = -1.0e9f;
                else if (qpos1 == kp) y = -1.0e5f;
                acc[nt][2+e] = y; m1 = fmaxf(m1, y);
            }
        }
        m0 = fmaxf(m0, __shfl_xor_sync(0xffffffffu, m0, 1));
        m0 = fmaxf(m0, __shfl_xor_sync(0xffffffffu, m0, 2));
        m1 = fmaxf(m1, __shfl_xor_sync(0xffffffffu, m1, 1));
        m1 = fmaxf(m1, __shfl_xor_sync(0xffffffffu, m1, 2));
        float s0 = 0.f, s1 = 0.f;
#pragma unroll
        for (int nt = 0; nt < 8; nt++)
#pragma unroll
            for (int e = 0; e < 2; e++) {
                float ex = __expf(acc[nt][e]   - m0); acc[nt][e]   = ex; s0 += ex;
                float ey = __expf(acc[nt][2+e] - m1); acc[nt][2+e] = ey; s1 += ey;
            }
        s0 += __shfl_xor_sync(0xffffffffu, s0, 1);
        s0 += __shfl_xor_sync(0xffffffffu, s0, 2);
        s1 += __shfl_xor_sync(0xffffffffu, s1, 1);
        s1 += __shfl_xor_sync(0xffffffffu, s1, 2);
        if ((l & 3) == 0) {
            statS[i0*2 + nh]       = make_float2(m0, s0);
            statS[(i0 + 8)*2 + nh] = make_float2(m1, s1);
        }
        __syncthreads();   // stats visible; all GEMM1 ksh reads done

        // ---- prefetch K(r+1) into ksh (overlaps softmax tail + GEMM2) ----
        if (r < R-1) {
            const int* kin = kiS + (r+1)*128;
#pragma unroll
            for (int it = 0; it < 4; it++) {
                int idx = it*256 + tid, row = idx >> 3, c8 = (idx & 7) << 3;
                cpa16(ks_s + (unsigned)row*(KSH_STR*2) + c8*2, &Qh[(size_t)kin[row]*D + c8]);
            }
            cpa_commit();
        }

        float2 ha = statS[i0*2],       hb = statS[i0*2 + 1];
        float M0 = fmaxf(ha.x, hb.x);
        float S0 = ha.y*__expf(ha.x - M0) + hb.y*__expf(hb.x - M0);
        float2 hc = statS[(i0+8)*2],   hd = statS[(i0+8)*2 + 1];
        float M1 = fmaxf(hc.x, hd.x);
        float S1 = hc.y*__expf(hc.x - M1) + hd.y*__expf(hd.x - M1);
        const float f0 = __expf(m0 - M0) / S0;
        const float f1 = __expf(m1 - M1) / S1;

        // ---- pack P into fp16 A-fragments (k16 chunks; no smem) ----
        unsigned ra[4][4];
#pragma unroll
        for (int t = 0; t < 4; t++) {
            int col0 = nh*64 + 16*t + 2*(l&3);
            float2 ci = *(float2*)&cinvS[r*128 + col0];
            float2 cj = *(float2*)&cinvS[r*128 + col0 + 8];
            ra[t][0] = h2u(acc[2*t][0]*f0*ci.x,   acc[2*t][1]*f0*ci.y);
            ra[t][1] = h2u(acc[2*t][2]*f1*ci.x,   acc[2*t][3]*f1*ci.y);
            ra[t][2] = h2u(acc[2*t+1][0]*f0*cj.x, acc[2*t+1][1]*f0*cj.y);
            ra[t][3] = h2u(acc[2*t+1][2]*f1*cj.x, acc[2*t+1][3]*f1*cj.y);
        }
        if (((l & 3) == 0) && nh == 0) {
            g_lse[((size_t)b*S + qpos0)*R + r] = M0 + __logf(S0);
            g_lse[((size_t)b*S + qpos1)*R + r] = M1 + __logf(S1);
        }

        // ---- V(r) ready ----
        if (r < R-1) cpa_wait1(); else cpa_wait0();
        __syncthreads();   // vsh visible; sred free (prev round's reads done)

        // ---- GEMM2 (fp16): warp computes all 64 dims over its 64-key half
        float acc2[8][4];
#pragma unroll
        for (int t2 = 0; t2 < 8; t2++)
#pragma unroll
            for (int c = 0; c < 4; c++) acc2[t2][c] = 0.f;

#pragma unroll
        for (int t = 0; t < 4; t++) {
#pragma unroll
            for (int p = 0; p < 4; p++) {          // dim tiles 2p, 2p+1
                unsigned b0,b1,b2,b3;
                ldsm4t(b0,b1,b2,b3, bG2 + (unsigned)(t*16*VSH_STR)*2 + p*32);
                mma_f16(acc2[2*p],   ra[t], b0, b1);
                mma_f16(acc2[2*p+1], ra[t], b2, b3);
            }
        }

        // ---- cross-warp k-half reduction via sred ----
        if (nh == 0) {
#pragma unroll
            for (int j = 0; j < 8; j++) {
                int c0 = j*8 + 2*(l&3);
                *(float2*)&sred[i0*SR_STR + c0]     = make_float2(acc2[j][0], acc2[j][1]);
                *(float2*)&sred[(i0+8)*SR_STR + c0] = make_float2(acc2[j][2], acc2[j][3]);
            }
        }
        __syncthreads();
        if (nh == 1) {
            __half* o0 = g_att + (((size_t)b*S + qpos0)*R + r)*D;
            __half* o1 = g_att + (((size_t)b*S + qpos1)*R + r)*D;
#pragma unroll
            for (int j = 0; j < 8; j++) {
                int c0 = j*8 + 2*(l&3);
                float2 p0 = *(float2*)&sred[i0*SR_STR + c0];
                float2 p1 = *(float2*)&sred[(i0+8)*SR_STR + c0];
                *(__half2*)&o0[c0] = __floats2half2_rn(acc2[j][0]+p0.x, acc2[j][1]+p0.y);
                *(__half2*)&o1[c0] = __floats2half2_rn(acc2[j][2]+p1.x, acc2[j][3]+p1.y);
            }
        }
        __syncthreads();   // all vsh + sred reads done

        // ---- prefetch V(r+1) into vsh (overlaps next round's GEMM1) ----
        if (r < R-1) {
            const int* kin = kiS + (r+1)*128;
#pragma unroll
            for (int it = 0; it < 4; it++) {
                int idx = it*256 + tid, row = idx >> 3, c8 = (idx & 7) << 3;
                cpa16(vs_s + (unsigned)row*(VSH_STR*2) + c8*2, &Vh[(size_t)kin[row]*D + c8]);
            }
            cpa_commit();
        }
    }
}

// ---------------- kernel 4: per-position round combine (fp16 att) --------
__global__ void __launch_bounds__(256) combine_kernel(float* __restrict__ out)
{
    const int tid = threadIdx.x;
    const int d2  = tid & 31;                       // half2 index (2 dims)
    const int row = blockIdx.x*8 + (tid >> 5);      // b*S + t
    float4 lv = *(const float4*)(g_lse + (size_t)row*R);
    float m  = fmaxf(fmaxf(lv.x, lv.y), fmaxf(lv.z, lv.w));
    float w0 = __expf(lv.x - m), w1 = __expf(lv.y - m);
    float w2 = __expf(lv.z - m), w3 = __expf(lv.w - m);
    float inv = 1.f / (w0 + w1 + w2 + w3);
    const __half2* a = (const __half2*)g_att + (size_t)row*R*(D/2);
    float2 a0 = __half22float2(a[0*(D/2) + d2]);
    float2 a1 = __half22float2(a[1*(D/2) + d2]);
    float2 a2 = __half22float2(a[2*(D/2) + d2]);
    float2 a3 = __half22float2(a[3*(D/2) + d2]);
    float2 res;
    res.x = (a0.x*w0 + a1.x*w1 + a2.x*w2 + a3.x*w3) * inv;
    res.y = (a0.y*w0 + a1.y*w1 + a2.y*w2 + a3.y*w3) * inv;
    *(float2*)&out[(size_t)row*D + d2*2] = res;
}

// ---------------- launch --------------------------------------------------
extern "C" void kernel_launch(void* const* d_in, const int* in_sizes, int n_in,
                              void* d_out, int out_size)
{
    const float* query = (const float*)d_in[0];
    const float* value = (const float*)d_in[1];
    const float* randm = (const float*)d_in[2];
    float* out = (float*)d_out;

    cudaFuncSetAttribute(hash_kernel,
                         cudaFuncAttributeMaxDynamicSharedMemorySize, HASH_SMEM);
    cudaFuncSetAttribute(attn_kernel,
                         cudaFuncAttributeMaxDynamicSharedMemorySize, ATTN_SMEM);

    vconv_kernel<<<(B*S*D)/(256*4), 256>>>(value);
    hash_kernel<<<dim3(S/128, B), 128, HASH_SMEM>>>(query, randm);
    sort_kernel<<<B*R, 256>>>();
    attn_kernel<<<B*NB, 256, ATTN_SMEM>>>();
    combine_kernel<<<(B*S)/8, 256>>>(out);
}

// round 11
// speedup vs baseline: 1.2846x; 1.2133x over previous
#include <cuda_runtime.h>
#include <cuda_fp16.h>
#include <math.h>

#define B  32
#define S  2048
#define D  64
#define R  4
#define NB 32

// ---------------- scratch (device globals; no allocation) ----------------
__device__ int    g_bucket[B*R*S];            // 1 MB
__device__ int    g_sortidx[B*R*S];           // 1 MB
__device__ float  g_qninv[B*S];               // 256 KB
__device__ __half g_qh[(size_t)B*S*D];        // 8 MB   fp16 copy of query
__device__ __half g_vh[(size_t)B*S*D];        // 8 MB   fp16 copy of value
__device__ __half g_att[(size_t)B*S*R*D];     // 32 MB  [b][t][r][d]
__device__ float  g_lse[B*S*R];               // 1 MB   [b][t][r]

// ---------------- mma / cp.async / ldmatrix helpers ----------------------
__device__ __forceinline__ void mma_f16(float* c, const unsigned* a,
                                        unsigned b0, unsigned b1)
{
    asm volatile(
        "mma.sync.aligned.m16n8k16.row.col.f32.f16.f16.f32 "
        "{%0,%1,%2,%3}, {%4,%5,%6,%7}, {%8,%9}, {%0,%1,%2,%3};"
        : "+f"(c[0]), "+f"(c[1]), "+f"(c[2]), "+f"(c[3])
        : "r"(a[0]), "r"(a[1]), "r"(a[2]), "r"(a[3]), "r"(b0), "r"(b1));
}

__device__ __forceinline__ void ldsm4(unsigned& r0, unsigned& r1,
                                      unsigned& r2, unsigned& r3, unsigned addr)
{
    asm volatile("ldmatrix.sync.aligned.m8n8.x4.shared.b16 {%0,%1,%2,%3}, [%4];"
                 : "=r"(r0), "=r"(r1), "=r"(r2), "=r"(r3) : "r"(addr));
}

__device__ __forceinline__ void ldsm4t(unsigned& r0, unsigned& r1,
                                       unsigned& r2, unsigned& r3, unsigned addr)
{
    asm volatile("ldmatrix.sync.aligned.m8n8.x4.trans.shared.b16 {%0,%1,%2,%3}, [%4];"
                 : "=r"(r0), "=r"(r1), "=r"(r2), "=r"(r3) : "r"(addr));
}

__device__ __forceinline__ void cpa16(unsigned dst, const void* src) {
    asm volatile("cp.async.cg.shared.global [%0], [%1], 16;" :: "r"(dst), "l"(src));
}
__device__ __forceinline__ void cpa_commit() { asm volatile("cp.async.commit_group;"); }
__device__ __forceinline__ void cpa_wait1()  { asm volatile("cp.async.wait_group 1;"); }
__device__ __forceinline__ void cpa_wait0()  { asm volatile("cp.async.wait_group 0;"); }

__device__ __forceinline__ unsigned h2u(float a, float b) {
    __half2 h = __floats2half2_rn(a, b);
    return *(unsigned*)&h;
}

// ---------------- kernel 1: hash + bucket + key norm + Q,V->fp16 ---------
#define SQ_STR 68
#define HASH_SMEM (128*SQ_STR*4 + 64*64*4)   // sQ[128][68] + sR[64][64]

__global__ void __launch_bounds__(128) hash_kernel(const float* __restrict__ query,
                                                   const float* __restrict__ value,
                                                   const float* __restrict__ randm)
{
    extern __shared__ float hs[];
    float* sQ = hs;                 // [128][68]
    float* sR = hs + 128*SQ_STR;    // [64][64]  d-major, rk = r*16+k
    const int b   = blockIdx.y;
    const int tid = threadIdx.x;

    for (int i = tid; i < 1024; i += 128)
        *(float4*)&sR[i*4] = *(const float4*)&randm[b*4096 + i*4];
    const size_t qbase = ((size_t)b*S + (size_t)blockIdx.x*128)*D;
    for (int i = tid; i < 2048; i += 128) {           // coalesced float4
        float4 v = *(const float4*)&query[qbase + (size_t)i*4];
        int row = i >> 4, d4 = (i & 15) << 2;
        *(float4*)&sQ[row*SQ_STR + d4] = v;
        uint2 h;                                      // emit fp16 Q copy
        h.x = h2u(v.x, v.y);
        h.y = h2u(v.z, v.w);
        *(uint2*)&g_qh[qbase + (size_t)i*4] = h;
    }
    for (int i = tid; i < 2048; i += 128) {           // fp16 V copy (fused)
        float4 v = *(const float4*)&value[qbase + (size_t)i*4];
        uint2 h;
        h.x = h2u(v.x, v.y);
        h.y = h2u(v.z, v.w);
        *(uint2*)&g_vh[qbase + (size_t)i*4] = h;
    }
    __syncthreads();

    const int t = blockIdx.x*128 + tid;
    const float* q = &sQ[tid*SQ_STR];

    float acc[64];
#pragma unroll
    for (int i = 0; i < 64; i++) acc[i] = 0.f;
    float nrm = 0.f;
    for (int d = 0; d < D; d++) {
        float qd = q[d];
        nrm += qd*qd;
        const float4* rr = (const float4*)&sR[d*64];
#pragma unroll
        for (int i4 = 0; i4 < 16; i4++) {
            float4 r4 = rr[i4];
            acc[i4*4+0] += qd * r4.x;
            acc[i4*4+1] += qd * r4.y;
            acc[i4*4+2] += qd * r4.z;
            acc[i4*4+3] += qd * r4.w;
        }
    }
    g_qninv[b*S + t] = rsqrtf(fmaxf(nrm, 1e-12f));

#pragma unroll
    for (int r = 0; r < R; r++) {
        float bv = acc[r*16];
        int   bi = 0;
#pragma unroll
        for (int k = 1; k < 16; k++) {
            float v = acc[r*16 + k];
            if (v > bv) { bv = v; bi = k; }
        }
#pragma unroll
        for (int k = 0; k < 16; k++) {
            float v = -acc[r*16 + k];
            if (v > bv) { bv = v; bi = 16 + k; }
        }
        g_bucket[(b*R + r)*S + t] = bi;
    }
}

// ---------------- kernel 2: stable counting sort per (b, r) --------------
__global__ void sort_kernel()
{
    __shared__ int hist[NB*256];   // bucket-major, thread-minor
    __shared__ int wtot[8];
    const int br  = blockIdx.x;
    const int tid = threadIdx.x;
    const int* bk = g_bucket  + br*S;
    int*     sidx = g_sortidx + br*S;

    for (int i = tid; i < NB*256; i += 256) hist[i] = 0;
    __syncthreads();

    const int base = tid*8;
    int myb[8];
#pragma unroll
    for (int k = 0; k < 8; k++) { myb[k] = bk[base + k]; hist[myb[k]*256 + tid]++; }
    __syncthreads();

    // exclusive scan over 8192 entries in index order (stable)
    int run = 0;
    for (int i = tid*32; i < tid*32 + 32; i++) { int v = hist[i]; hist[i] = run; run += v; }
    const int lane = tid & 31, wid = tid >> 5;
    int x = run;
#pragma unroll
    for (int off = 1; off < 32; off <<= 1) {
        int nv = __shfl_up_sync(0xffffffffu, x, off);
        if (lane >= off) x += nv;
    }
    if (lane == 31) wtot[wid] = x;
    __syncthreads();
    if (tid < 8) {
        int y = wtot[tid], z = y;
#pragma unroll
        for (int off = 1; off < 8; off <<= 1) {
            int nv = __shfl_up_sync(0x000000ffu, z, off);
            if (tid >= off) z += nv;
        }
        wtot[tid] = z - y;    // exclusive warp offsets
    }
    __syncthreads();
    const int add = (x - run) + wtot[wid];
    for (int i = tid*32; i < tid*32 + 32; i++) hist[i] += add;
    __syncthreads();

#pragma unroll
    for (int k = 0; k < 8; k++) {
        int bb  = myb[k];
        int rnk = hist[bb*256 + tid]++;
        sidx[rnk] = base + k;
    }
}

// ---------------- kernel 3: bucketed attention, 4 warps, full-n per warp -
// All-fp16 MMA. Each warp owns 16 rows x all 128 cols: P stays in registers
// across GEMM1->softmax->GEMM2; no cross-warp exchange at all.
// smem layout (bytes):
//   [0,2048)        kiS   : int[512]          window key positions, per round
//   [2048,4096)     cinvS : float[512]        1/duplicate-count
//   [4096,6144)     scS   : float[512]        per-key qn*0.125 scale
//   [6144,28672)    ksh   : half[128][88]     Q/K window tile (rows 64.. = Q)
//   [28672,51200)   vsh   : half[128][88]     V tile (cnt int[2048] aliases
//                                              during phase 0, before V0 load)
#define KSH_STR 88
#define VSH_STR 88
#define OFF_KI    0
#define OFF_CINV  2048
#define OFF_SC    4096
#define OFF_KS    6144
#define OFF_VS    28672
#define ATTN_SMEM 51200

__global__ void __launch_bounds__(128, 4) attn_kernel()
{
    extern __shared__ char smem[];
    int*    kiS   = (int*)   (smem + OFF_KI);
    float*  cinvS = (float*) (smem + OFF_CINV);
    float*  scS   = (float*) (smem + OFF_SC);
    int*    cnt   = (int*)   (smem + OFF_VS);   // alias (phase 0 only)

    const int blk = blockIdx.x;
    const int b   = blk >> 5;
    const int n   = blk & 31;
    const int tid = threadIdx.x;
    const int l   = tid & 31;
    const int mi  = tid >> 5;   // warp = m-tile (16 rows)

    const int* sidx_b = g_sortidx + b*R*S;
    const int  prev   = (n + 31) & 31;
    const float* qn   = g_qninv + b*S;
    const __half* Qh  = g_qh + (size_t)b*S*D;
    const __half* Vh  = g_vh + (size_t)b*S*D;

    const unsigned ks_s = (unsigned)__cvta_generic_to_shared(smem + OFF_KS);
    const unsigned vs_s = (unsigned)__cvta_generic_to_shared(smem + OFF_VS);
    const int i0 = mi*16 + (l>>2);

    // per-lane ldmatrix base addresses (bytes)
    const unsigned aG1 = ks_s + (unsigned)((64 + mi*16 + (l & 15))*KSH_STR)*2
                              + ((l >> 4) << 4);
    const unsigned bG1 = ks_s + (unsigned)(((l & 7) + ((l & 16) >> 1))*KSH_STR)*2
                              + (((l >> 3) & 1) << 4);
    const unsigned bG2 = vs_s + (unsigned)((l & 15)*VSH_STR)*2 + ((l >> 4) << 4);

    // ---- phase 0a: window key positions ----
    for (int idx = tid; idx < 512; idx += 128) {
        int r = idx >> 7, j = idx & 127;
        int slot = (j < 64) ? (prev*64 + j) : (n*64 + j - 64);
        kiS[idx] = sidx_b[r*S + slot];
    }
    __syncthreads();

    // ---- prologue: K0 load starts now (overlaps counting) ----
    {
        const int* ki = kiS;
#pragma unroll
        for (int it = 0; it < 8; it++) {         // 1024 x 16B
            int idx = it*128 + tid, row = idx >> 3, c8 = (idx & 7) << 3;
            cpa16(ks_s + (unsigned)row*(KSH_STR*2) + c8*2, &Qh[(size_t)ki[row]*D + c8]);
        }
        cpa_commit();
    }

    // ---- phase 0b: multiplicity counts + scales (cnt lives in vsh) ----
    for (int idx = tid; idx < 2048; idx += 128) cnt[idx] = 0;
    __syncthreads();
    for (int idx = tid; idx < 512; idx += 128) atomicAdd(&cnt[kiS[idx]], 1);
    __syncthreads();
    for (int idx = tid; idx < 512; idx += 128) {
        int kp = kiS[idx];
        cinvS[idx] = 1.f / (float)cnt[kp];
        scS[idx]   = qn[kp] * 0.125f;
    }
    __syncthreads();   // all cnt reads done; vsh free for V0

    // ---- prologue: V0 load ----
    {
        const int* ki = kiS;
#pragma unroll
        for (int it = 0; it < 8; it++) {
            int idx = it*128 + tid, row = idx >> 3, c8 = (idx & 7) << 3;
            cpa16(vs_s + (unsigned)row*(VSH_STR*2) + c8*2, &Vh[(size_t)ki[row]*D + c8]);
        }
        cpa_commit();
    }

    for (int r = 0; r < R; r++) {
        const int* ki = kiS + r*128;

        // ---- K(r) ready (oldest outstanding group) ----
        cpa_wait1();
        __syncthreads();

        // ---- GEMM1 (fp16): S[16x128] per warp = Q(rows 64..127) . K^T ----
        float acc[16][4];
#pragma unroll
        for (int t2 = 0; t2 < 16; t2++)
#pragma unroll
            for (int c = 0; c < 4; c++) acc[t2][c] = 0.f;

        unsigned af[4][4];                           // A frags, 4 k16 chunks
#pragma unroll
        for (int c = 0; c < 4; c++)
            ldsm4(af[c][0], af[c][1], af[c][2], af[c][3], aG1 + c*32);

#pragma unroll
        for (int p = 0; p < 8; p++) {                // n-tile pairs 2p, 2p+1
#pragma unroll
            for (int c = 0; c < 4; c++) {            // k16 chunks
                unsigned b0,b1,b2,b3;
                ldsm4(b0,b1,b2,b3, bG1 + (unsigned)(p*16*KSH_STR)*2 + c*32);
                mma_f16(acc[2*p],   af[c], b0, b1);
                mma_f16(acc[2*p+1], af[c], b2, b3);
            }
        }
        __syncthreads();   // all warps' ksh reads done

        // ---- prefetch K(r+1) into ksh (overlaps softmax + GEMM2) ----
        if (r < R-1) {
            const int* kin = kiS + (r+1)*128;
#pragma unroll
            for (int it = 0; it < 8; it++) {
                int idx = it*128 + tid, row = idx >> 3, c8 = (idx & 7) << 3;
                cpa16(ks_s + (unsigned)row*(KSH_STR*2) + c8*2, &Qh[(size_t)kin[row]*D + c8]);
            }
            cpa_commit();
        }

        // ---- in-register scale + masks + softmax (single warp per row) --
        const int qpos0 = ki[64 + i0];
        const int qpos1 = ki[64 + i0 + 8];
        float m0 = -3.4e38f, m1 = -3.4e38f;
#pragma unroll
        for (int nt = 0; nt < 16; nt++) {
#pragma unroll
            for (int e = 0; e < 2; e++) {
                int col = nt*8 + 2*(l&3) + e;
                int kp  = ki[col];
                float sc = scS[r*128 + col];
                float x = acc[nt][e] * sc;
                if      (qpos0 <  kp) x = -1.0e9f;
                else if (qpos0 == kp) x = -1.0e5f;
                acc[nt][e] = x; m0 = fmaxf(m0, x);
                float y = acc[nt][2+e] * sc;
                if      (qpos1 <  kp) y = -1.0e9f;
                else if (qpos1 == kp) y = -1.0e5f;
                acc[nt][2+e] = y; m1 = fmaxf(m1, y);
            }
        }
        m0 = fmaxf(m0, __shfl_xor_sync(0xffffffffu, m0, 1));
        m0 = fmaxf(m0, __shfl_xor_sync(0xffffffffu, m0, 2));
        m1 = fmaxf(m1, __shfl_xor_sync(0xffffffffu, m1, 1));
        m1 = fmaxf(m1, __shfl_xor_sync(0xffffffffu, m1, 2));
        float s0 = 0.f, s1 = 0.f;
#pragma unroll
        for (int nt = 0; nt < 16; nt++)
#pragma unroll
            for (int e = 0; e < 2; e++) {
                float ex = __expf(acc[nt][e]   - m0); acc[nt][e]   = ex; s0 += ex;
                float ey = __expf(acc[nt][2+e] - m1); acc[nt][2+e] = ey; s1 += ey;
            }
        s0 += __shfl_xor_sync(0xffffffffu, s0, 1);
        s0 += __shfl_xor_sync(0xffffffffu, s0, 2);
        s1 += __shfl_xor_sync(0xffffffffu, s1, 1);
        s1 += __shfl_xor_sync(0xffffffffu, s1, 2);
        const float f0 = 1.f / s0;
        const float f1 = 1.f / s1;

        // ---- pack P into fp16 A-fragments (8 k16 chunks; no smem) ----
        unsigned ra[8][4];
#pragma unroll
        for (int t = 0; t < 8; t++) {
            int col0 = 16*t + 2*(l&3);
            float2 ci = *(float2*)&cinvS[r*128 + col0];
            float2 cj = *(float2*)&cinvS[r*128 + col0 + 8];
            ra[t][0] = h2u(acc[2*t][0]*f0*ci.x,   acc[2*t][1]*f0*ci.y);
            ra[t][1] = h2u(acc[2*t][2]*f1*ci.x,   acc[2*t][3]*f1*ci.y);
            ra[t][2] = h2u(acc[2*t+1][0]*f0*cj.x, acc[2*t+1][1]*f0*cj.y);
            ra[t][3] = h2u(acc[2*t+1][2]*f1*cj.x, acc[2*t+1][3]*f1*cj.y);
        }
        if ((l & 3) == 0) {
            g_lse[((size_t)b*S + qpos0)*R + r] = m0 + __logf(s0);
            g_lse[((size_t)b*S + qpos1)*R + r] = m1 + __logf(s1);
        }

        // ---- V(r) ready ----
        if (r < R-1) cpa_wait1(); else cpa_wait0();
        __syncthreads();

        // ---- GEMM2 (fp16): full 128-key k per warp, all 64 dims ----
        float acc2[8][4];
#pragma unroll
        for (int t2 = 0; t2 < 8; t2++)
#pragma unroll
            for (int c = 0; c < 4; c++) acc2[t2][c] = 0.f;

#pragma unroll
        for (int t = 0; t < 8; t++) {              // k16 chunks over 128 keys
#pragma unroll
            for (int p = 0; p < 4; p++) {          // dim tiles 2p, 2p+1
                unsigned b0,b1,b2,b3;
                ldsm4t(b0,b1,b2,b3, bG2 + (unsigned)(t*16*VSH_STR)*2 + p*32);
                mma_f16(acc2[2*p],   ra[t], b0, b1);
                mma_f16(acc2[2*p+1], ra[t], b2, b3);
            }
        }

        __half* o0 = g_att + (((size_t)b*S + qpos0)*R + r)*D;
        __half* o1 = g_att + (((size_t)b*S + qpos1)*R + r)*D;
#pragma unroll
        for (int j = 0; j < 8; j++) {
            int c0 = j*8 + 2*(l&3);
            *(__half2*)&o0[c0] = __floats2half2_rn(acc2[j][0], acc2[j][1]);
            *(__half2*)&o1[c0] = __floats2half2_rn(acc2[j][2], acc2[j][3]);
        }
        __syncthreads();   // all vsh reads done

        // ---- prefetch V(r+1) into vsh (overlaps next round's GEMM1) ----
        if (r < R-1) {
            const int* kin = kiS + (r+1)*128;
#pragma unroll
            for (int it = 0; it < 8; it++) {
                int idx = it*128 + tid, row = idx >> 3, c8 = (idx & 7) << 3;
                cpa16(vs_s + (unsigned)row*(VSH_STR*2) + c8*2, &Vh[(size_t)kin[row]*D + c8]);
            }
            cpa_commit();
        }
    }
}

// ---------------- kernel 4: round combine, 2 rows per thread -------------
__global__ void __launch_bounds__(256) combine_kernel(float* __restrict__ out)
{
    const int tid = threadIdx.x;
    const int l   = tid & 31;                       // half2 index (2 dims)
    const int w   = tid >> 5;
    const int r0  = blockIdx.x*16 + w;              // b*S + t
    const int r1  = r0 + 8;

    float4 la = *(const float4*)(g_lse + (size_t)r0*R);
    float4 lb = *(const float4*)(g_lse + (size_t)r1*R);
    const __half2* a = (const __half2*)g_att + (size_t)r0*R*(D/2);
    const __half2* c = (const __half2*)g_att + (size_t)r1*R*(D/2);
    __half2 av0 = a[0*(D/2)+l], av1 = a[1*(D/2)+l], av2 = a[2*(D/2)+l], av3 = a[3*(D/2)+l];
    __half2 cv0 = c[0*(D/2)+l], cv1 = c[1*(D/2)+l], cv2 = c[2*(D/2)+l], cv3 = c[3*(D/2)+l];

    {
        float m  = fmaxf(fmaxf(la.x, la.y), fmaxf(la.z, la.w));
        float w0 = __expf(la.x - m), w1 = __expf(la.y - m);
        float w2 = __expf(la.z - m), w3 = __expf(la.w - m);
        float inv = 1.f / (w0 + w1 + w2 + w3);
        float2 a0 = __half22float2(av0), a1 = __half22float2(av1);
        float2 a2 = __half22float2(av2), a3 = __half22float2(av3);
        float2 res;
        res.x = (a0.x*w0 + a1.x*w1 + a2.x*w2 + a3.x*w3) * inv;
        res.y = (a0.y*w0 + a1.y*w1 + a2.y*w2 + a3.y*w3) * inv;
        *(float2*)&out[(size_t)r0*D + l*2] = res;
    }
    {
        float m  = fmaxf(fmaxf(lb.x, lb.y), fmaxf(lb.z, lb.w));
        float w0 = __expf(lb.x - m), w1 = __expf(lb.y - m);
        float w2 = __expf(lb.z - m), w3 = __expf(lb.w - m);
        float inv = 1.f / (w0 + w1 + w2 + w3);
        float2 a0 = __half22float2(cv0), a1 = __half22float2(cv1);
        float2 a2 = __half22float2(cv2), a3 = __half22float2(cv3);
        float2 res;
        res.x = (a0.x*w0 + a1.x*w1 + a2.x*w2 + a3.x*w3) * inv;
        res.y = (a0.y*w0 + a1.y*w1 + a2.y*w2 + a3.y*w3) * inv;
        *(float2*)&out[(size_t)r1*D + l*2] = res;
    }
}

// ---------------- launch --------------------------------------------------
extern "C" void kernel_launch(void* const* d_in, const int* in_sizes, int n_in,
                              void* d_out, int out_size)
{
    const float* query = (const float*)d_in[0];
    const float* value = (const float*)d_in[1];
    const float* randm = (const float*)d_in[2];
    float* out = (float*)d_out;

    cudaFuncSetAttribute(hash_kernel,
                         cudaFuncAttributeMaxDynamicSharedMemorySize, HASH_SMEM);
    cudaFuncSetAttribute(attn_kernel,
                         cudaFuncAttributeMaxDynamicSharedMemorySize, ATTN_SMEM);

    hash_kernel<<<dim3(S/128, B), 128, HASH_SMEM>>>(query, value, randm);
    sort_kernel<<<B*R, 256>>>();
    attn_kernel<<<B*NB, 128, ATTN_SMEM>>>();
    combine_kernel<<<(B*S)/16, 256>>>(out);
}